// round 4
// baseline (speedup 1.0000x reference)
#include <cuda_runtime.h>

#define T_LEN 2048
typedef unsigned long long u64;

// ---- MUFU helpers ----
__device__ __forceinline__ float ex2f(float x){ float y; asm("ex2.approx.f32 %0, %1;" : "=f"(y) : "f"(x)); return y; }
__device__ __forceinline__ float rcpf(float x){ float y; asm("rcp.approx.f32 %0, %1;" : "=f"(y) : "f"(x)); return y; }

// ---- packed f32x2 helpers (sm_100+) ----
__device__ __forceinline__ u64 pk(float lo, float hi){ u64 d; asm("mov.b64 %0, {%1, %2};" : "=l"(d) : "f"(lo), "f"(hi)); return d; }
__device__ __forceinline__ void unpk(u64 d, float& lo, float& hi){ asm("mov.b64 {%0, %1}, %2;" : "=f"(lo), "=f"(hi) : "l"(d)); }
__device__ __forceinline__ u64 fma2_(u64 a, u64 b, u64 c){ u64 d; asm("fma.rn.f32x2 %0, %1, %2, %3;" : "=l"(d) : "l"(a), "l"(b), "l"(c)); return d; }
__device__ __forceinline__ u64 mul2_(u64 a, u64 b){ u64 d; asm("mul.rn.f32x2 %0, %1, %2;" : "=l"(d) : "l"(a), "l"(b)); return d; }
__device__ __forceinline__ u64 add2_(u64 a, u64 b){ u64 d; asm("add.rn.f32x2 %0, %1, %2;" : "=l"(d) : "l"(a), "l"(b)); return d; }

// Full gate-quad LSTM activation for one unit.
// IFp = (pre_i, pre_f) already scaled by -log2e; GOp = (pre_g, pre_o) scaled
// by (+2log2e, -log2e). c is carried state. Returns h, updates c.
__device__ __forceinline__ float lstm_act(u64 IFp, u64 GOp, float& c) {
    const float PL = 2.8853900817779268f;  // 2*log2(e)
    float pi, pf, pg, po;
    unpk(IFp, pi, pf); unpk(GOp, pg, po);
    const float di = 1.f + ex2f(pi), df = 1.f + ex2f(pf);
    const float dg = 1.f + ex2f(pg), dn = 1.f + ex2f(po);
    const float rIF = rcpf(di * df), rGO = rcpf(dg * dn);
    const float I = rIF * df, F = rIF * di;
    const float s = rGO * dn, O = rGO * dg;     // s = sigmoid-like; tanh(g) = 1-2s
    c = fmaf(F, c, I * fmaf(-2.f, s, 1.f));
    return O * fmaf(-2.f, rcpf(ex2f(PL * c) + 1.f), 1.f);
}

// 16 lanes per batch element. Lane g (0..15), unit j = g&7:
//   g < 8 : owns gate rows (i_j, f_j) of BOTH layers, carries c1_j
//   g >= 8: owns gate rows (g_j, o_j) of BOTH layers, carries c2_j
// Each lane computes its packed gate-pair pre-activations for L1(t) and
// L2(t-1); one shfl_xor(8) swaps halves so low lanes run the L1 activation
// while high lanes concurrently run the L2 activation. h1/h2 are then
// broadcast (width-16 shfl) and kept duplicated-packed for the dots.
// 2048 warps -> ~3.5 warps/SMSP: hides the recurrence latency.
__global__ void __launch_bounds__(64) lstm2_fused_kernel(
    const float* __restrict__ x,
    const float* __restrict__ w_ih1, const float* __restrict__ w_hh1,
    const float* __restrict__ b_ih1, const float* __restrict__ b_hh1,
    const float* __restrict__ w_ih2, const float* __restrict__ w_hh2,
    const float* __restrict__ b_ih2, const float* __restrict__ b_hh2,
    const float* __restrict__ fc_w, const float* __restrict__ fc_b,
    float* __restrict__ out, int B)
{
    const int tid  = blockIdx.x * blockDim.x + threadIdx.x;
    const int bat  = tid >> 4;
    if (bat >= B) return;
    const int g    = tid & 15;
    const int half = g >> 3;                  // 0: IF rows, 1: GO rows
    const int j    = g & 7;
    const unsigned FULL = 0xffffffffu;

    const float L2E = 1.4426950408889634f;
    const float NL  = -L2E;                   // sigmoid rows
    const float PL  = 2.0f * L2E;             // tanh rows

    // rows owned by this lane (same row indices for both layers)
    const int r0 = half ? (16 + j) : j;       // i_j  or  g_j
    const int r1 = half ? (24 + j) : (8 + j); // f_j  or  o_j
    const float s0 = half ? PL : NL;          // g-row gets +2log2e
    const float s1 = NL;                      // f/o rows sigmoid

    // ---- fold scales into packed weights (one-time) ----
    u64 wh1p[8], wx2p[8], wh2p[8];
    #pragma unroll
    for (int k = 0; k < 8; k++) {
        wh1p[k] = pk(s0 * w_hh1[r0*8+k], s1 * w_hh1[r1*8+k]);
        wx2p[k] = pk(s0 * w_ih2[r0*8+k], s1 * w_ih2[r1*8+k]);
        wh2p[k] = pk(s0 * w_hh2[r0*8+k], s1 * w_hh2[r1*8+k]);
    }
    const u64 wx1p = pk(s0 * w_ih1[r0], s1 * w_ih1[r1]);
    const u64 bb1p = pk(s0 * (b_ih1[r0] + b_hh1[r0]), s1 * (b_ih1[r1] + b_hh1[r1]));
    const u64 bb2p = pk(s0 * (b_ih2[r0] + b_hh2[r0]), s1 * (b_ih2[r1] + b_hh2[r1]));

    // ---- state ----
    float c = 0.0f;                           // c1_j (low) or c2_j (high)
    u64 H1[8], H2[8];                         // duplicated-packed h vectors

    const float* xb = x + (size_t)bat * T_LEN;

    // ---- prologue: L1 step 0 (h1 = c1 = 0) ----
    {
        const float x0 = __ldg(&xb[0]);
        u64 a = fma2_(wx1p, pk(x0, x0), bb1p);
        u64 recv = __shfl_xor_sync(FULL, a, 8);
        u64 IFp = half ? recv : a;
        u64 GOp = half ? a : recv;
        float c0 = 0.0f;
        float h = lstm_act(IFp, GOp, c0);     // h1_j(0), identical on both halves
        c = half ? 0.0f : c0;                 // low keeps c1; high starts c2 = 0
        #pragma unroll
        for (int k = 0; k < 8; k++) {
            float v = __shfl_sync(FULL, h, k, 16);
            H1[k] = pk(v, v);
            H2[k] = pk(0.f, 0.f);
        }
    }

    float xt_next = __ldg(&xb[1]);

    // ---- main loop: iteration t computes L1(t) and L2(t-1) ----
    #pragma unroll 1
    for (int t = 1; t < T_LEN; t++) {
        const float xt = xt_next;
        xt_next = __ldg(&xb[(t + 1) & (T_LEN - 1)]);   // wraps harmlessly
        const u64 XT = pk(xt, xt);

        // L1(t) packed pre-acts: bb1 + wx1*x + wh1 . H1 (two 4-chains)
        u64 a0 = fma2_(wx1p, XT, bb1p);
        #pragma unroll
        for (int k = 0; k < 4; k++) a0 = fma2_(wh1p[k], H1[k], a0);
        u64 a1 = mul2_(wh1p[4], H1[4]);
        #pragma unroll
        for (int k = 5; k < 8; k++) a1 = fma2_(wh1p[k], H1[k], a1);
        const u64 a = add2_(a0, a1);

        // L2(t-1) packed pre-acts: bb2 + wh2 . H2 + wx2 . H1 (four 4-chains)
        u64 e0 = fma2_(wh2p[0], H2[0], bb2p);
        #pragma unroll
        for (int k = 1; k < 4; k++) e0 = fma2_(wh2p[k], H2[k], e0);
        u64 e1 = mul2_(wh2p[4], H2[4]);
        #pragma unroll
        for (int k = 5; k < 8; k++) e1 = fma2_(wh2p[k], H2[k], e1);
        u64 e2 = mul2_(wx2p[0], H1[0]);
        #pragma unroll
        for (int k = 1; k < 4; k++) e2 = fma2_(wx2p[k], H1[k], e2);
        u64 e3 = mul2_(wx2p[4], H1[4]);
        #pragma unroll
        for (int k = 5; k < 8; k++) e3 = fma2_(wx2p[k], H1[k], e3);
        const u64 e = add2_(add2_(e0, e1), add2_(e2, e3));

        // ---- swap halves: low lane gets L1-GO, high lane gets L2-IF ----
        const u64 send = half ? a : e;
        const u64 recv = __shfl_xor_sync(FULL, send, 8);
        const u64 IFp = half ? recv : a;
        const u64 GOp = half ? e : recv;

        // low lanes: L1 activation (h1_j(t)); high lanes: L2 activation (h2_j(t-1))
        const float h = lstm_act(IFp, GOp, c);

        // ---- broadcast h1 (from low lanes) and h2 (from high lanes) ----
        #pragma unroll
        for (int k = 0; k < 8; k++) {
            float v1 = __shfl_sync(FULL, h, k,     16);
            float v2 = __shfl_sync(FULL, h, 8 + k, 16);
            H1[k] = pk(v1, v1);
            H2[k] = pk(v2, v2);
        }
    }

    // ---- epilogue: L2(T-1) on high lanes ----
    float h2last;
    {
        u64 e0 = fma2_(wh2p[0], H2[0], bb2p);
        #pragma unroll
        for (int k = 1; k < 4; k++) e0 = fma2_(wh2p[k], H2[k], e0);
        u64 e1 = mul2_(wh2p[4], H2[4]);
        #pragma unroll
        for (int k = 5; k < 8; k++) e1 = fma2_(wh2p[k], H2[k], e1);
        u64 e2 = mul2_(wx2p[0], H1[0]);
        #pragma unroll
        for (int k = 1; k < 4; k++) e2 = fma2_(wx2p[k], H1[k], e2);
        u64 e3 = mul2_(wx2p[4], H1[4]);
        #pragma unroll
        for (int k = 5; k < 8; k++) e3 = fma2_(wx2p[k], H1[k], e3);
        const u64 e = add2_(add2_(e0, e1), add2_(e2, e3));

        const u64 recv = __shfl_xor_sync(FULL, e, 8);
        const u64 IFp = half ? recv : e;      // only high lanes' result is used
        const u64 GOp = half ? e : recv;
        h2last = lstm_act(IFp, GOp, c);       // valid on high lanes (c = c2_j)
    }

    // ---- fc on final h2 (gather from high lanes; low lanes j<4 write) ----
    float h2f[8];
    #pragma unroll
    for (int k = 0; k < 8; k++) h2f[k] = __shfl_sync(FULL, h2last, 8 + k, 16);
    if (g < 4) {
        float acc = fc_b[j];
        #pragma unroll
        for (int k = 0; k < 8; k++) acc = fmaf(fc_w[j*8+k], h2f[k], acc);
        out[bat*4 + j] = acc;
    }
}

extern "C" void kernel_launch(void* const* d_in, const int* in_sizes, int n_in,
                              void* d_out, int out_size)
{
    const float* x     = (const float*)d_in[0];
    const float* w_ih1 = (const float*)d_in[1];
    const float* w_hh1 = (const float*)d_in[2];
    const float* b_ih1 = (const float*)d_in[3];
    const float* b_hh1 = (const float*)d_in[4];
    const float* w_ih2 = (const float*)d_in[5];
    const float* w_hh2 = (const float*)d_in[6];
    const float* b_ih2 = (const float*)d_in[7];
    const float* b_hh2 = (const float*)d_in[8];
    const float* fc_w  = (const float*)d_in[9];
    const float* fc_b  = (const float*)d_in[10];
    float* out = (float*)d_out;

    const int B = in_sizes[0] / T_LEN;      // 4096
    const int threads = B * 16;             // 65536 -> 2048 warps
    const int block = 64;                   // 1024 CTAs, ~7/SM balanced
    const int grid = (threads + block - 1) / block;

    lstm2_fused_kernel<<<grid, block>>>(x, w_ih1, w_hh1, b_ih1, b_hh1,
                                        w_ih2, w_hh2, b_ih2, b_hh2,
                                        fc_w, fc_b, out, B);
}

// round 5
// speedup vs baseline: 1.1384x; 1.1384x over previous
#include <cuda_runtime.h>

#define T_LEN 2048
typedef unsigned long long u64;

// ---- MUFU helpers ----
__device__ __forceinline__ float ex2f(float x){ float y; asm("ex2.approx.f32 %0, %1;" : "=f"(y) : "f"(x)); return y; }
__device__ __forceinline__ float rcpf(float x){ float y; asm("rcp.approx.f32 %0, %1;" : "=f"(y) : "f"(x)); return y; }

// ---- packed f32x2 helpers (sm_100+) ----
__device__ __forceinline__ u64 pk(float lo, float hi){ u64 d; asm("mov.b64 %0, {%1, %2};" : "=l"(d) : "f"(lo), "f"(hi)); return d; }
__device__ __forceinline__ void unpk(u64 d, float& lo, float& hi){ asm("mov.b64 {%0, %1}, %2;" : "=f"(lo), "=f"(hi) : "l"(d)); }
__device__ __forceinline__ u64 fma2_(u64 a, u64 b, u64 c){ u64 d; asm("fma.rn.f32x2 %0, %1, %2, %3;" : "=l"(d) : "l"(a), "l"(b), "l"(c)); return d; }
__device__ __forceinline__ u64 mul2_(u64 a, u64 b){ u64 d; asm("mul.rn.f32x2 %0, %1, %2;" : "=l"(d) : "l"(a), "l"(b)); return d; }
__device__ __forceinline__ u64 add2_(u64 a, u64 b){ u64 d; asm("add.rn.f32x2 %0, %1, %2;" : "=l"(d) : "l"(a), "l"(b)); return d; }

// Full gate-quad LSTM activation for one unit.
// IFp = (pre_i, pre_f) scaled by -log2e; GOp = (pre_g, pre_o) scaled by
// (+2log2e, -log2e). c is carried state. Returns h, updates c.
__device__ __forceinline__ float lstm_act(u64 IFp, u64 GOp, float& c) {
    const float PL = 2.8853900817779268f;  // 2*log2(e)
    float pi, pf, pg, po;
    unpk(IFp, pi, pf); unpk(GOp, pg, po);
    const float di = 1.f + ex2f(pi), df = 1.f + ex2f(pf);
    const float dg = 1.f + ex2f(pg), dn = 1.f + ex2f(po);
    const float rIF = rcpf(di * df), rGO = rcpf(dg * dn);
    const float I = rIF * df, F = rIF * di;
    const float s = rGO * dn, O = rGO * dg;     // tanh(g) = 1 - 2s
    c = fmaf(F, c, I * fmaf(-2.f, s, 1.f));
    return O * fmaf(-2.f, rcpf(ex2f(PL * c) + 1.f), 1.f);
}

// 16 lanes per batch element. Lane g (0..15), unit j = g&7:
//   g < 8 : owns gate rows (i_j, f_j) of BOTH layers, carries c1_j
//   g >= 8: owns gate rows (g_j, o_j) of BOTH layers, carries c2_j
// Each lane computes its packed gate-pair pre-activations for L1(t) and
// L2(t-1); one shfl_xor(8) swaps halves so low lanes run the L1 activation
// while high lanes run L2. h1/h2 are exchanged through a double-buffered
// SMEM region (STS.64 + syncwarp + LDS.128) instead of 16 shuffles — the
// shuffle/MIO pipe was the R4 bottleneck.
__global__ void __launch_bounds__(64) lstm2_fused_kernel(
    const float* __restrict__ x,
    const float* __restrict__ w_ih1, const float* __restrict__ w_hh1,
    const float* __restrict__ b_ih1, const float* __restrict__ b_hh1,
    const float* __restrict__ w_ih2, const float* __restrict__ w_hh2,
    const float* __restrict__ b_ih2, const float* __restrict__ b_hh2,
    const float* __restrict__ fc_w, const float* __restrict__ fc_b,
    float* __restrict__ out, int B)
{
    const int tid  = blockIdx.x * blockDim.x + threadIdx.x;
    const int bat  = tid >> 4;
    if (bat >= B) return;
    const int g    = tid & 15;
    const int half = g >> 3;                  // 0: IF rows, 1: GO rows
    const int j    = g & 7;
    const unsigned FULL = 0xffffffffu;

    const float L2E = 1.4426950408889634f;
    const float NL  = -L2E;                   // sigmoid rows
    const float PL  = 2.0f * L2E;             // tanh rows

    // rows owned by this lane (same row indices for both layers)
    const int r0 = half ? (16 + j) : j;       // i_j  or  g_j
    const int r1 = half ? (24 + j) : (8 + j); // f_j  or  o_j
    const float s0 = half ? PL : NL;
    const float s1 = NL;

    // ---- fold scales into packed weights (one-time) ----
    u64 wh1p[8], wx2p[8], wh2p[8];
    #pragma unroll
    for (int k = 0; k < 8; k++) {
        wh1p[k] = pk(s0 * w_hh1[r0*8+k], s1 * w_hh1[r1*8+k]);
        wx2p[k] = pk(s0 * w_ih2[r0*8+k], s1 * w_ih2[r1*8+k]);
        wh2p[k] = pk(s0 * w_hh2[r0*8+k], s1 * w_hh2[r1*8+k]);
    }
    const u64 wx1p = pk(s0 * w_ih1[r0], s1 * w_ih1[r1]);
    const u64 bb1p = pk(s0 * (b_ih1[r0] + b_hh1[r0]), s1 * (b_ih1[r1] + b_hh1[r1]));
    const u64 bb2p = pk(s0 * (b_ih2[r0] + b_hh2[r0]), s1 * (b_ih2[r1] + b_hh2[r1]));

    // ---- SMEM h-exchange: [buf][group][H1(0..7) | H2(8..15)] ----
    __shared__ __align__(16) u64 hbuf[2][4][16];
    const int  gidx = threadIdx.x >> 4;       // group within CTA (0..3)
    u64* const grp0 = &hbuf[0][gidx][0];
    u64* const grp1 = &hbuf[1][gidx][0];
    const int  slot = half * 8 + j;

    // ---- state ----
    float c = 0.0f;                           // c1_j (low) or c2_j (high)
    u64 H1[8], H2[8];

    const float* xb = x + (size_t)bat * T_LEN;

    // ---- prologue ("t=0"): L1 step 0 (h1 = c1 = 0), h2(-1) = 0 ----
    {
        const float x0 = __ldg(&xb[0]);
        u64 a = fma2_(wx1p, pk(x0, x0), bb1p);
        u64 recv = __shfl_xor_sync(FULL, a, 8);
        u64 IFp = half ? recv : a;
        u64 GOp = half ? a : recv;
        float c0 = 0.0f;
        float h = lstm_act(IFp, GOp, c0);     // h1_j(0) on both halves
        c = half ? 0.0f : c0;
        const float hs = half ? 0.0f : h;     // high half stores h2(-1) = 0
        grp0[slot] = pk(hs, hs);
        __syncwarp();
        const ulonglong2* v = (const ulonglong2*)grp0;
        #pragma unroll
        for (int m = 0; m < 4; m++) { ulonglong2 t2 = v[m];     H1[2*m] = t2.x; H1[2*m+1] = t2.y; }
        #pragma unroll
        for (int m = 0; m < 4; m++) { ulonglong2 t2 = v[4 + m]; H2[2*m] = t2.x; H2[2*m+1] = t2.y; }
    }

    float xt_next = __ldg(&xb[1]);

    // ---- main loop: iteration t computes L1(t) and L2(t-1) ----
    #pragma unroll 2
    for (int t = 1; t < T_LEN; t++) {
        const float xt = xt_next;
        xt_next = __ldg(&xb[(t + 1) & (T_LEN - 1)]);   // wraps harmlessly
        const u64 XT = pk(xt, xt);

        // L1(t) packed pre-acts: bb1 + wx1*x + wh1 . H1 (two 4-chains)
        u64 a0 = fma2_(wx1p, XT, bb1p);
        #pragma unroll
        for (int k = 0; k < 4; k++) a0 = fma2_(wh1p[k], H1[k], a0);
        u64 a1 = mul2_(wh1p[4], H1[4]);
        #pragma unroll
        for (int k = 5; k < 8; k++) a1 = fma2_(wh1p[k], H1[k], a1);
        const u64 a = add2_(a0, a1);

        // L2(t-1) packed pre-acts: bb2 + wh2 . H2 + wx2 . H1 (four 4-chains)
        u64 e0 = fma2_(wh2p[0], H2[0], bb2p);
        #pragma unroll
        for (int k = 1; k < 4; k++) e0 = fma2_(wh2p[k], H2[k], e0);
        u64 e1 = mul2_(wh2p[4], H2[4]);
        #pragma unroll
        for (int k = 5; k < 8; k++) e1 = fma2_(wh2p[k], H2[k], e1);
        u64 e2 = mul2_(wx2p[0], H1[0]);
        #pragma unroll
        for (int k = 1; k < 4; k++) e2 = fma2_(wx2p[k], H1[k], e2);
        u64 e3 = mul2_(wx2p[4], H1[4]);
        #pragma unroll
        for (int k = 5; k < 8; k++) e3 = fma2_(wx2p[k], H1[k], e3);
        const u64 e = add2_(add2_(e0, e1), add2_(e2, e3));

        // ---- swap halves: low lane gets L1-GO, high lane gets L2-IF ----
        const u64 send = half ? a : e;
        const u64 recv = __shfl_xor_sync(FULL, send, 8);
        const u64 IFp = half ? recv : a;
        const u64 GOp = half ? e : recv;

        // low lanes: L1 activation -> h1_j(t); high lanes: L2 -> h2_j(t-1)
        const float h = lstm_act(IFp, GOp, c);

        // ---- exchange via double-buffered SMEM ----
        u64* const dst = (t & 1) ? grp1 : grp0;
        dst[slot] = pk(h, h);
        __syncwarp();
        const ulonglong2* v = (const ulonglong2*)dst;
        #pragma unroll
        for (int m = 0; m < 4; m++) { ulonglong2 t2 = v[m];     H1[2*m] = t2.x; H1[2*m+1] = t2.y; }
        #pragma unroll
        for (int m = 0; m < 4; m++) { ulonglong2 t2 = v[4 + m]; H2[2*m] = t2.x; H2[2*m+1] = t2.y; }
    }

    // ---- epilogue: L2(T-1) on high lanes ----
    float h2last;
    {
        u64 e0 = fma2_(wh2p[0], H2[0], bb2p);
        #pragma unroll
        for (int k = 1; k < 4; k++) e0 = fma2_(wh2p[k], H2[k], e0);
        u64 e1 = mul2_(wh2p[4], H2[4]);
        #pragma unroll
        for (int k = 5; k < 8; k++) e1 = fma2_(wh2p[k], H2[k], e1);
        u64 e2 = mul2_(wx2p[0], H1[0]);
        #pragma unroll
        for (int k = 1; k < 4; k++) e2 = fma2_(wx2p[k], H1[k], e2);
        u64 e3 = mul2_(wx2p[4], H1[4]);
        #pragma unroll
        for (int k = 5; k < 8; k++) e3 = fma2_(wx2p[k], H1[k], e3);
        const u64 e = add2_(add2_(e0, e1), add2_(e2, e3));

        const u64 recv = __shfl_xor_sync(FULL, e, 8);
        const u64 IFp = half ? recv : e;      // only high lanes' result matters
        const u64 GOp = half ? e : recv;
        h2last = lstm_act(IFp, GOp, c);       // valid on high lanes (c = c2_j)
    }

    // ---- fc on final h2 (gather from high lanes; low lanes j<4 write) ----
    float h2f[8];
    #pragma unroll
    for (int k = 0; k < 8; k++) h2f[k] = __shfl_sync(FULL, h2last, 8 + k, 16);
    if (g < 4) {
        float acc = fc_b[j];
        #pragma unroll
        for (int k = 0; k < 8; k++) acc = fmaf(fc_w[j*8+k], h2f[k], acc);
        out[bat*4 + j] = acc;
    }
}

extern "C" void kernel_launch(void* const* d_in, const int* in_sizes, int n_in,
                              void* d_out, int out_size)
{
    const float* x     = (const float*)d_in[0];
    const float* w_ih1 = (const float*)d_in[1];
    const float* w_hh1 = (const float*)d_in[2];
    const float* b_ih1 = (const float*)d_in[3];
    const float* b_hh1 = (const float*)d_in[4];
    const float* w_ih2 = (const float*)d_in[5];
    const float* w_hh2 = (const float*)d_in[6];
    const float* b_ih2 = (const float*)d_in[7];
    const float* b_hh2 = (const float*)d_in[8];
    const float* fc_w  = (const float*)d_in[9];
    const float* fc_b  = (const float*)d_in[10];
    float* out = (float*)d_out;

    const int B = in_sizes[0] / T_LEN;      // 4096
    const int threads = B * 16;             // 65536 -> 2048 warps
    const int block = 64;                   // 1024 CTAs, ~7/SM balanced
    const int grid = (threads + block - 1) / block;

    lstm2_fused_kernel<<<grid, block>>>(x, w_ih1, w_hh1, b_ih1, b_hh1,
                                        w_ih2, w_hh2, b_ih2, b_hh2,
                                        fc_w, fc_b, out, B);
}

// round 6
// speedup vs baseline: 1.1389x; 1.0004x over previous
#include <cuda_runtime.h>

#define T_LEN 2048
typedef unsigned long long u64;

// ---- MUFU helpers ----
__device__ __forceinline__ float ex2f(float x){ float y; asm("ex2.approx.f32 %0, %1;" : "=f"(y) : "f"(x)); return y; }
__device__ __forceinline__ float rcpf(float x){ float y; asm("rcp.approx.f32 %0, %1;" : "=f"(y) : "f"(x)); return y; }

// ---- packed f32x2 helpers (sm_100+) ----
__device__ __forceinline__ u64 pk(float lo, float hi){ u64 d; asm("mov.b64 %0, {%1, %2};" : "=l"(d) : "f"(lo), "f"(hi)); return d; }
__device__ __forceinline__ void unpk(u64 d, float& lo, float& hi){ asm("mov.b64 {%0, %1}, %2;" : "=f"(lo), "=f"(hi) : "l"(d)); }
__device__ __forceinline__ u64 fma2_(u64 a, u64 b, u64 c){ u64 d; asm("fma.rn.f32x2 %0, %1, %2, %3;" : "=l"(d) : "l"(a), "l"(b), "l"(c)); return d; }
__device__ __forceinline__ u64 mul2_(u64 a, u64 b){ u64 d; asm("mul.rn.f32x2 %0, %1, %2;" : "=l"(d) : "l"(a), "l"(b)); return d; }
__device__ __forceinline__ u64 add2_(u64 a, u64 b){ u64 d; asm("add.rn.f32x2 %0, %1, %2;" : "=l"(d) : "l"(a), "l"(b)); return d; }

// 2-warp producer/consumer barrier (warp-specialized; both warps execute
// exactly T_LEN barriers).
#define BARRIER() asm volatile("bar.sync 0, 64;" ::: "memory")

// CTA = 64 threads = 2 warps serving 4 batch elements.
//   warp 0 (producer): layer-1 LSTM, 8 lanes per batch, lane j owns gate rows
//                      {j, j+8, j+16, j+24} packed as (i,f)/(g,o) pairs.
//   warp 1 (consumer): layer-2, one timestep behind (classic software pipeline,
//                      now split ACROSS warps so each warp's per-step chain and
//                      instruction stream are ~half of the fused version).
// h1 / h2 are exchanged via double-buffered SMEM (STS.64 + LDS.128) with one
// 2-warp bar.sync per step. All arithmetic is operation-identical to the best
// fused kernel, so rel_err is expected unchanged (~1.39e-7).
__global__ void __launch_bounds__(64, 7) lstm2_ab_kernel(
    const float* __restrict__ x,
    const float* __restrict__ w_ih1, const float* __restrict__ w_hh1,
    const float* __restrict__ b_ih1, const float* __restrict__ b_hh1,
    const float* __restrict__ w_ih2, const float* __restrict__ w_hh2,
    const float* __restrict__ b_ih2, const float* __restrict__ b_hh2,
    const float* __restrict__ fc_w, const float* __restrict__ fc_b,
    float* __restrict__ out, int B)
{
    const int wid  = threadIdx.x >> 5;        // 0 = L1 producer, 1 = L2 consumer
    const int lane = threadIdx.x & 31;
    const int grp  = lane >> 3;               // batch group within CTA (0..3)
    const int j    = lane & 7;                // hidden unit owned by this lane
    const int bat  = blockIdx.x * 4 + grp;
    const int base = lane & 24;
    const unsigned FULL = 0xffffffffu;

    const float L2E = 1.4426950408889634f;
    const float NL  = -L2E;                   // sigmoid rows: exp(-a)=2^(NL*a)
    const float PL  = 2.0f * L2E;             // tanh rows:    exp(2a)=2^(PL*a)
    const int gi = j, gf = j + 8, gg = j + 16, go = j + 24;

    // double-buffered h exchange: [parity][group][unit], duplicated-packed u64
    __shared__ __align__(16) u64 h1buf[2][4][8];
    __shared__ __align__(16) u64 h2buf[2][4][8];

    // h1(-1) = 0 lives in h1buf[1]; h2(-1) = 0 lives in h2buf[0]
    if (threadIdx.x < 32) {
        ((u64*)h1buf[1])[threadIdx.x] = 0ull;
        ((u64*)h2buf[0])[threadIdx.x] = 0ull;
    }
    __syncthreads();

    if (wid == 0) {
        // ================= producer: layer-1 =================
        u64 whIF1[8], whGO1[8];
        #pragma unroll
        for (int k = 0; k < 8; k++) {
            whIF1[k] = pk(NL * w_hh1[gi*8+k], NL * w_hh1[gf*8+k]);
            whGO1[k] = pk(PL * w_hh1[gg*8+k], NL * w_hh1[go*8+k]);
        }
        const u64 wx1IF = pk(NL * w_ih1[gi], NL * w_ih1[gf]);
        const u64 wx1GO = pk(PL * w_ih1[gg], NL * w_ih1[go]);
        const u64 bIF1  = pk(NL*(b_ih1[gi]+b_hh1[gi]), NL*(b_ih1[gf]+b_hh1[gf]));
        const u64 bGO1  = pk(PL*(b_ih1[gg]+b_hh1[gg]), NL*(b_ih1[go]+b_hh1[go]));

        float c1 = 0.0f;
        const float* xb = x + (size_t)bat * T_LEN;
        float xt_next = __ldg(&xb[0]);

        #pragma unroll 2
        for (int t = 0; t < T_LEN; t++) {
            const float xt = xt_next;
            xt_next = __ldg(&xb[(t + 1) & (T_LEN - 1)]);   // wraps harmlessly
            const int p = t & 1, q = p ^ 1;                // q holds h1(t-1)

            u64 H1[8];
            const ulonglong2* v = (const ulonglong2*)&h1buf[q][grp][0];
            #pragma unroll
            for (int m = 0; m < 4; m++) { ulonglong2 t2 = v[m]; H1[2*m] = t2.x; H1[2*m+1] = t2.y; }

            const u64 XT = pk(xt, xt);
            u64 aIF0 = fma2_(wx1IF, XT, bIF1);
            u64 aGO0 = fma2_(wx1GO, XT, bGO1);
            #pragma unroll
            for (int k = 0; k < 4; k++) { aIF0 = fma2_(whIF1[k], H1[k], aIF0); aGO0 = fma2_(whGO1[k], H1[k], aGO0); }
            u64 aIF1 = mul2_(whIF1[4], H1[4]);
            u64 aGO1 = mul2_(whGO1[4], H1[4]);
            #pragma unroll
            for (int k = 5; k < 8; k++) { aIF1 = fma2_(whIF1[k], H1[k], aIF1); aGO1 = fma2_(whGO1[k], H1[k], aGO1); }

            float a_i, a_f, a_g, a_o;
            unpk(add2_(aIF0, aIF1), a_i, a_f);
            unpk(add2_(aGO0, aGO1), a_g, a_o);
            const float d1i = 1.f + ex2f(a_i), d1f = 1.f + ex2f(a_f);
            const float d1g = 1.f + ex2f(a_g), d1o = 1.f + ex2f(a_o);
            const float r1IF = rcpf(d1i * d1f), r1GO = rcpf(d1g * d1o);
            const float I1 = r1IF * d1f, F1 = r1IF * d1i;
            const float s1 = r1GO * d1o, O1 = r1GO * d1g;
            c1 = fmaf(F1, c1, I1 * fmaf(-2.f, s1, 1.f));
            const float h1j = O1 * fmaf(-2.f, rcpf(ex2f(PL * c1) + 1.f), 1.f);

            h1buf[p][grp][j] = pk(h1j, h1j);
            BARRIER();
        }
    } else {
        // ================= consumer: layer-2 (one step behind) =================
        u64 whIF2[8], whGO2[8], wxIF2[8], wxGO2[8];
        #pragma unroll
        for (int k = 0; k < 8; k++) {
            whIF2[k] = pk(NL * w_hh2[gi*8+k], NL * w_hh2[gf*8+k]);
            whGO2[k] = pk(PL * w_hh2[gg*8+k], NL * w_hh2[go*8+k]);
            wxIF2[k] = pk(NL * w_ih2[gi*8+k], NL * w_ih2[gf*8+k]);
            wxGO2[k] = pk(PL * w_ih2[gg*8+k], NL * w_ih2[go*8+k]);
        }
        const u64 bIF2 = pk(NL*(b_ih2[gi]+b_hh2[gi]), NL*(b_ih2[gf]+b_hh2[gf]));
        const u64 bGO2 = pk(PL*(b_ih2[gg]+b_hh2[gg]), NL*(b_ih2[go]+b_hh2[go]));

        float c2 = 0.0f;
        float h2j = 0.0f;

        BARRIER();                                         // pairs with producer t=0

        #pragma unroll 2
        for (int t = 1; t < T_LEN; t++) {                  // computes L2(t-1)
            const int p = t & 1, q = p ^ 1;                // q: h1(t-1), h2(t-2)

            u64 H1[8], H2[8];
            const ulonglong2* v1 = (const ulonglong2*)&h1buf[q][grp][0];
            const ulonglong2* v2 = (const ulonglong2*)&h2buf[q][grp][0];
            #pragma unroll
            for (int m = 0; m < 4; m++) { ulonglong2 t2 = v1[m]; H1[2*m] = t2.x; H1[2*m+1] = t2.y; }
            #pragma unroll
            for (int m = 0; m < 4; m++) { ulonglong2 t2 = v2[m]; H2[2*m] = t2.x; H2[2*m+1] = t2.y; }

            u64 eIF0 = bIF2, eGO0 = bGO2;
            #pragma unroll
            for (int k = 0; k < 8; k++) { eIF0 = fma2_(whIF2[k], H2[k], eIF0); eGO0 = fma2_(whGO2[k], H2[k], eGO0); }
            u64 eIF1 = mul2_(wxIF2[0], H1[0]);
            u64 eGO1 = mul2_(wxGO2[0], H1[0]);
            #pragma unroll
            for (int k = 1; k < 8; k++) { eIF1 = fma2_(wxIF2[k], H1[k], eIF1); eGO1 = fma2_(wxGO2[k], H1[k], eGO1); }

            float e_i, e_f, e_g, e_o;
            unpk(add2_(eIF0, eIF1), e_i, e_f);
            unpk(add2_(eGO0, eGO1), e_g, e_o);
            const float d2i = 1.f + ex2f(e_i), d2f = 1.f + ex2f(e_f);
            const float d2g = 1.f + ex2f(e_g), d2o = 1.f + ex2f(e_o);
            const float r2IF = rcpf(d2i * d2f), r2GO = rcpf(d2g * d2o);
            const float I2 = r2IF * d2f, F2 = r2IF * d2i;
            const float s2 = r2GO * d2o, O2 = r2GO * d2g;
            c2 = fmaf(F2, c2, I2 * fmaf(-2.f, s2, 1.f));
            h2j = O2 * fmaf(-2.f, rcpf(ex2f(PL * c2) + 1.f), 1.f);

            h2buf[p][grp][j] = pk(h2j, h2j);
            BARRIER();
        }

        // ---- final step: L2(T-1). h1(T-1) and h2(T-2) are both in parity 1 ----
        {
            u64 H1[8], H2[8];
            const ulonglong2* v1 = (const ulonglong2*)&h1buf[1][grp][0];
            const ulonglong2* v2 = (const ulonglong2*)&h2buf[1][grp][0];
            #pragma unroll
            for (int m = 0; m < 4; m++) { ulonglong2 t2 = v1[m]; H1[2*m] = t2.x; H1[2*m+1] = t2.y; }
            #pragma unroll
            for (int m = 0; m < 4; m++) { ulonglong2 t2 = v2[m]; H2[2*m] = t2.x; H2[2*m+1] = t2.y; }

            u64 eIF0 = bIF2, eGO0 = bGO2;
            #pragma unroll
            for (int k = 0; k < 8; k++) { eIF0 = fma2_(whIF2[k], H2[k], eIF0); eGO0 = fma2_(whGO2[k], H2[k], eGO0); }
            u64 eIF1 = mul2_(wxIF2[0], H1[0]);
            u64 eGO1 = mul2_(wxGO2[0], H1[0]);
            #pragma unroll
            for (int k = 1; k < 8; k++) { eIF1 = fma2_(wxIF2[k], H1[k], eIF1); eGO1 = fma2_(wxGO2[k], H1[k], eGO1); }

            float e_i, e_f, e_g, e_o;
            unpk(add2_(eIF0, eIF1), e_i, e_f);
            unpk(add2_(eGO0, eGO1), e_g, e_o);
            const float d2i = 1.f + ex2f(e_i), d2f = 1.f + ex2f(e_f);
            const float d2g = 1.f + ex2f(e_g), d2o = 1.f + ex2f(e_o);
            const float r2IF = rcpf(d2i * d2f), r2GO = rcpf(d2g * d2o);
            const float I2 = r2IF * d2f, F2 = r2IF * d2i;
            const float s2 = r2GO * d2o, O2 = r2GO * d2g;
            c2 = fmaf(F2, c2, I2 * fmaf(-2.f, s2, 1.f));
            h2j = O2 * fmaf(-2.f, rcpf(ex2f(PL * c2) + 1.f), 1.f);
        }

        // ---- fc on final h2 ----
        float h2f[8];
        #pragma unroll
        for (int k = 0; k < 8; k++) h2f[k] = __shfl_sync(FULL, h2j, base + k);
        if (j < 4) {
            float acc = fc_b[j];
            #pragma unroll
            for (int k = 0; k < 8; k++) acc = fmaf(fc_w[j*8+k], h2f[k], acc);
            out[bat*4 + j] = acc;
        }
    }
}

extern "C" void kernel_launch(void* const* d_in, const int* in_sizes, int n_in,
                              void* d_out, int out_size)
{
    const float* x     = (const float*)d_in[0];
    const float* w_ih1 = (const float*)d_in[1];
    const float* w_hh1 = (const float*)d_in[2];
    const float* b_ih1 = (const float*)d_in[3];
    const float* b_hh1 = (const float*)d_in[4];
    const float* w_ih2 = (const float*)d_in[5];
    const float* w_hh2 = (const float*)d_in[6];
    const float* b_ih2 = (const float*)d_in[7];
    const float* b_hh2 = (const float*)d_in[8];
    const float* fc_w  = (const float*)d_in[9];
    const float* fc_b  = (const float*)d_in[10];
    float* out = (float*)d_out;

    const int B = in_sizes[0] / T_LEN;      // 4096
    const int grid = B / 4;                 // 1024 CTAs of 2 warps (~7/SM)

    lstm2_ab_kernel<<<grid, 64>>>(x, w_ih1, w_hh1, b_ih1, b_hh1,
                                  w_ih2, w_hh2, b_ih2, b_hh2,
                                  fc_w, fc_b, out, B);
}

// round 7
// speedup vs baseline: 1.7540x; 1.5401x over previous
#include <cuda_runtime.h>

#define T_LEN 2048
typedef unsigned long long u64;

// ---- MUFU.TANH (sm_75+): 1 MUFU op per activation ----
__device__ __forceinline__ float tanha(float x){ float y; asm("tanh.approx.f32 %0, %1;" : "=f"(y) : "f"(x)); return y; }

// ---- packed f32x2 helpers (sm_100+) ----
__device__ __forceinline__ u64 pk(float lo, float hi){ u64 d; asm("mov.b64 %0, {%1, %2};" : "=l"(d) : "f"(lo), "f"(hi)); return d; }
__device__ __forceinline__ void unpk(u64 d, float& lo, float& hi){ asm("mov.b64 {%0, %1}, %2;" : "=f"(lo), "=f"(hi) : "l"(d)); }
__device__ __forceinline__ u64 fma2_(u64 a, u64 b, u64 c){ u64 d; asm("fma.rn.f32x2 %0, %1, %2, %3;" : "=l"(d) : "l"(a), "l"(b), "l"(c)); return d; }
__device__ __forceinline__ u64 mul2_(u64 a, u64 b){ u64 d; asm("mul.rn.f32x2 %0, %1, %2;" : "=l"(d) : "l"(a), "l"(b)); return d; }
__device__ __forceinline__ u64 add2_(u64 a, u64 b){ u64 d; asm("add.rn.f32x2 %0, %1, %2;" : "=l"(d) : "l"(a), "l"(b)); return d; }

// Best-known layout (R2): 8 lanes per batch; lane j owns gate rows
// {j, j+8, j+16, j+24} of both layers, packed (i,f)/(g,o). Layers
// software-pipelined: iteration t computes L1(t) and L2(t-1).
// NEW: all activations via MUFU.TANH. sigmoid(x) = 0.5*tanh(0.5x)+0.5 with
// the 0.5 pre-scale folded into weights/biases (i,f,o rows scaled by 0.5;
// g row unscaled for direct tanh). MUFU per warp-step: 20 -> 10; the
// ex2/rcp activation tower (~110 cyc serial/layer) becomes ~45 cyc.
__global__ void __launch_bounds__(128) lstm2_fused_kernel(
    const float* __restrict__ x,
    const float* __restrict__ w_ih1, const float* __restrict__ w_hh1,
    const float* __restrict__ b_ih1, const float* __restrict__ b_hh1,
    const float* __restrict__ w_ih2, const float* __restrict__ w_hh2,
    const float* __restrict__ b_ih2, const float* __restrict__ b_hh2,
    const float* __restrict__ fc_w, const float* __restrict__ fc_b,
    float* __restrict__ out, int B)
{
    const int tid = blockIdx.x * blockDim.x + threadIdx.x;
    const int b   = tid >> 3;
    if (b >= B) return;
    const int j   = tid & 7;
    const unsigned FULL = 0xffffffffu;

    const float HF = 0.5f;   // sigmoid rows: sigma(a) = 0.5*tanh(0.5a)+0.5
    const int gi = j, gf = j + 8, gg = j + 16, go = j + 24;

    // ---- fold scales into packed weights (one-time) ----
    // IF pairs: both rows x0.5 (sigmoid). GO pairs: g row x1 (tanh), o row x0.5.
    u64 whIF1[8], whGO1[8], wxIF2[8], wxGO2[8], whIF2[8], whGO2[8];
    #pragma unroll
    for (int k = 0; k < 8; k++) {
        whIF1[k] = pk(HF * w_hh1[gi*8+k], HF * w_hh1[gf*8+k]);
        whGO1[k] = pk(     w_hh1[gg*8+k], HF * w_hh1[go*8+k]);
        wxIF2[k] = pk(HF * w_ih2[gi*8+k], HF * w_ih2[gf*8+k]);
        wxGO2[k] = pk(     w_ih2[gg*8+k], HF * w_ih2[go*8+k]);
        whIF2[k] = pk(HF * w_hh2[gi*8+k], HF * w_hh2[gf*8+k]);
        whGO2[k] = pk(     w_hh2[gg*8+k], HF * w_hh2[go*8+k]);
    }
    const u64 wx1IF = pk(HF * w_ih1[gi], HF * w_ih1[gf]);
    const u64 wx1GO = pk(     w_ih1[gg], HF * w_ih1[go]);
    const u64 bIF1  = pk(HF*(b_ih1[gi]+b_hh1[gi]), HF*(b_ih1[gf]+b_hh1[gf]));
    const u64 bGO1  = pk(    (b_ih1[gg]+b_hh1[gg]), HF*(b_ih1[go]+b_hh1[go]));
    const u64 bIF2  = pk(HF*(b_ih2[gi]+b_hh2[gi]), HF*(b_ih2[gf]+b_hh2[gf]));
    const u64 bGO2  = pk(    (b_ih2[gg]+b_hh2[gg]), HF*(b_ih2[go]+b_hh2[go]));

    // ---- state ----
    float c1, c2 = 0.0f;
    u64 H1[8], H2[8];

    const float* xb = x + (size_t)b * T_LEN;

    // ---- prologue: L1 step 0 (h1 = c1 = 0) ----
    {
        const float x0 = __ldg(&xb[0]);
        float ai, af, ag, ao;
        unpk(fma2_(wx1IF, pk(x0, x0), bIF1), ai, af);
        unpk(fma2_(wx1GO, pk(x0, x0), bGO1), ag, ao);
        const float I = fmaf(0.5f, tanha(ai), 0.5f);
        const float G = tanha(ag);
        const float O = fmaf(0.5f, tanha(ao), 0.5f);
        c1 = I * G;
        const float h1j = O * tanha(c1);
        #pragma unroll
        for (int k = 0; k < 8; k++) {
            float v = __shfl_sync(FULL, h1j, k, 8);
            H1[k] = pk(v, v);
            H2[k] = pk(0.f, 0.f);
        }
    }

    float xt_next = __ldg(&xb[1]);

    // ---- main loop: iteration t does L1(t) and L2(t-1) concurrently ----
    #pragma unroll 2
    for (int t = 1; t < T_LEN; t++) {
        const float xt = xt_next;
        xt_next = __ldg(&xb[(t + 1) & (T_LEN - 1)]);   // wraps harmlessly
        const u64 XT = pk(xt, xt);

        // L1(t) pre-acts: b1 + wx1*x + wh1 . H1 (two parallel 4-chains)
        u64 aIF0 = fma2_(wx1IF, XT, bIF1);
        u64 aGO0 = fma2_(wx1GO, XT, bGO1);
        #pragma unroll
        for (int k = 0; k < 4; k++) {
            aIF0 = fma2_(whIF1[k], H1[k], aIF0);
            aGO0 = fma2_(whGO1[k], H1[k], aGO0);
        }
        u64 aIF1 = mul2_(whIF1[4], H1[4]);
        u64 aGO1 = mul2_(whGO1[4], H1[4]);
        #pragma unroll
        for (int k = 5; k < 8; k++) {
            aIF1 = fma2_(whIF1[k], H1[k], aIF1);
            aGO1 = fma2_(whGO1[k], H1[k], aGO1);
        }
        const u64 aIF = add2_(aIF0, aIF1);
        const u64 aGO = add2_(aGO0, aGO1);

        // L2(t-1) pre-acts: b2 + wh2 . H2 + wx2 . H1 (two parallel 8-chains)
        u64 eIF0 = bIF2, eGO0 = bGO2;
        #pragma unroll
        for (int k = 0; k < 8; k++) {
            eIF0 = fma2_(whIF2[k], H2[k], eIF0);
            eGO0 = fma2_(whGO2[k], H2[k], eGO0);
        }
        u64 eIF1 = mul2_(wxIF2[0], H1[0]);
        u64 eGO1 = mul2_(wxGO2[0], H1[0]);
        #pragma unroll
        for (int k = 1; k < 8; k++) {
            eIF1 = fma2_(wxIF2[k], H1[k], eIF1);
            eGO1 = fma2_(wxGO2[k], H1[k], eGO1);
        }
        const u64 eIF = add2_(eIF0, eIF1);
        const u64 eGO = add2_(eGO0, eGO1);

        // ---- L1 activations: 5 MUFU.TANH ----
        float a_i, a_f, a_g, a_o; unpk(aIF, a_i, a_f); unpk(aGO, a_g, a_o);
        const float I1 = fmaf(0.5f, tanha(a_i), 0.5f);
        const float F1 = fmaf(0.5f, tanha(a_f), 0.5f);
        const float G1 = tanha(a_g);
        const float O1 = fmaf(0.5f, tanha(a_o), 0.5f);
        c1 = fmaf(F1, c1, I1 * G1);
        const float h1j = O1 * tanha(c1);

        // ---- L2 activations: 5 MUFU.TANH ----
        float e_i, e_f, e_g, e_o; unpk(eIF, e_i, e_f); unpk(eGO, e_g, e_o);
        const float I2 = fmaf(0.5f, tanha(e_i), 0.5f);
        const float F2 = fmaf(0.5f, tanha(e_f), 0.5f);
        const float G2 = tanha(e_g);
        const float O2 = fmaf(0.5f, tanha(e_o), 0.5f);
        c2 = fmaf(F2, c2, I2 * G2);
        const float h2j = O2 * tanha(c2);

        // ---- broadcast h1_t, h2_{t-1} within the 8-lane group ----
        #pragma unroll
        for (int k = 0; k < 8; k++) {
            float v1 = __shfl_sync(FULL, h1j, k, 8);
            float v2 = __shfl_sync(FULL, h2j, k, 8);
            H1[k] = pk(v1, v1);
            H2[k] = pk(v2, v2);
        }
    }

    // ---- epilogue: L2(T-1) ----
    float h2j;
    {
        u64 eIF0 = bIF2, eGO0 = bGO2;
        #pragma unroll
        for (int k = 0; k < 8; k++) {
            eIF0 = fma2_(whIF2[k], H2[k], eIF0);
            eGO0 = fma2_(whGO2[k], H2[k], eGO0);
        }
        u64 eIF1 = mul2_(wxIF2[0], H1[0]);
        u64 eGO1 = mul2_(wxGO2[0], H1[0]);
        #pragma unroll
        for (int k = 1; k < 8; k++) {
            eIF1 = fma2_(wxIF2[k], H1[k], eIF1);
            eGO1 = fma2_(wxGO2[k], H1[k], eGO1);
        }
        float e_i, e_f, e_g, e_o;
        unpk(add2_(eIF0, eIF1), e_i, e_f);
        unpk(add2_(eGO0, eGO1), e_g, e_o);
        const float I2 = fmaf(0.5f, tanha(e_i), 0.5f);
        const float F2 = fmaf(0.5f, tanha(e_f), 0.5f);
        const float G2 = tanha(e_g);
        const float O2 = fmaf(0.5f, tanha(e_o), 0.5f);
        c2 = fmaf(F2, c2, I2 * G2);
        h2j = O2 * tanha(c2);
    }

    // ---- fc on final h2 ----
    float h2f[8];
    #pragma unroll
    for (int k = 0; k < 8; k++) h2f[k] = __shfl_sync(FULL, h2j, k, 8);
    if (j < 4) {
        float acc = fc_b[j];
        #pragma unroll
        for (int k = 0; k < 8; k++) acc = fmaf(fc_w[j*8+k], h2f[k], acc);
        out[b*4 + j] = acc;
    }
}

extern "C" void kernel_launch(void* const* d_in, const int* in_sizes, int n_in,
                              void* d_out, int out_size)
{
    const float* x     = (const float*)d_in[0];
    const float* w_ih1 = (const float*)d_in[1];
    const float* w_hh1 = (const float*)d_in[2];
    const float* b_ih1 = (const float*)d_in[3];
    const float* b_hh1 = (const float*)d_in[4];
    const float* w_ih2 = (const float*)d_in[5];
    const float* w_hh2 = (const float*)d_in[6];
    const float* b_ih2 = (const float*)d_in[7];
    const float* b_hh2 = (const float*)d_in[8];
    const float* fc_w  = (const float*)d_in[9];
    const float* fc_b  = (const float*)d_in[10];
    float* out = (float*)d_out;

    const int B = in_sizes[0] / T_LEN;      // 4096
    const int threads = B * 8;              // 8 lanes per batch element
    const int block = 128;                  // best-known config (R2)
    const int grid = (threads + block - 1) / block;

    lstm2_fused_kernel<<<grid, block>>>(x, w_ih1, w_hh1, b_ih1, b_hh1,
                                        w_ih2, w_hh2, b_ih2, b_hh2,
                                        fc_w, fc_b, out, B);
}

// round 9
// speedup vs baseline: 1.8766x; 1.0699x over previous
#include <cuda_runtime.h>

#define T_LEN 2048
typedef unsigned long long u64;

// ---- MUFU.TANH (1 MUFU per activation) ----
__device__ __forceinline__ float tanha(float x){ float y; asm("tanh.approx.f32 %0, %1;" : "=f"(y) : "f"(x)); return y; }

// ---- packed f32x2 helpers (sm_100+) ----
__device__ __forceinline__ u64 pk(float lo, float hi){ u64 d; asm("mov.b64 %0, {%1, %2};" : "=l"(d) : "f"(lo), "f"(hi)); return d; }
__device__ __forceinline__ void unpk(u64 d, float& lo, float& hi){ asm("mov.b64 {%0, %1}, %2;" : "=f"(lo), "=f"(hi) : "l"(d)); }
__device__ __forceinline__ u64 fma2_(u64 a, u64 b, u64 c){ u64 d; asm("fma.rn.f32x2 %0, %1, %2, %3;" : "=l"(d) : "l"(a), "l"(b), "l"(c)); return d; }
__device__ __forceinline__ u64 mul2_(u64 a, u64 b){ u64 d; asm("mul.rn.f32x2 %0, %1, %2;" : "=l"(d) : "l"(a), "l"(b)); return d; }
__device__ __forceinline__ u64 add2_(u64 a, u64 b){ u64 d; asm("add.rn.f32x2 %0, %1, %2;" : "=l"(d) : "l"(a), "l"(b)); return d; }

// Refactored activation: inputs are pre-scaled preacts (sigmoid rows x0.5,
// tanh row x1, with an extra x0.5 on all h-consuming weights because h is
// carried as h2x = 2h). Returns h2x; updates true c in place.
__device__ __forceinline__ float lstm_act(float a_i, float a_f, float a_g, float a_o, float& c) {
    const float thi = tanha(a_i), thf = tanha(a_f);
    const float thg = tanha(a_g), tho = tanha(a_o);
    const float F  = fmaf(0.5f, thf, 0.5f);
    const float g2 = fmaf(thi, thg, thg);           // 2*sigmoid(i)*tanh(g)
    c = fmaf(F, c, 0.5f * g2);
    const float thc = tanha(c);
    return fmaf(tho, thc, thc);                      // h2x = 2*sigmoid(o)*tanh(c)
}

// Best-known layout (R7): 8 lanes per batch; lane j owns gate rows
// {j, j+8, j+16, j+24} of both layers, packed (i,f)/(g,o). Layers
// software-pipelined: iteration t computes L1(t) and L2(t-1).
// NEW vs R7:
//  * h broadcast via padded SMEM (2x STS.32 duplicated + 8x LDS.64 per
//    vector, double-buffered, one syncwarp/step) replacing 16 SHFL + 16 pk.
//  * output-gate fold: h carried as 2h, 0.5 folded into h-consuming weights.
__global__ void __launch_bounds__(128) lstm2_fused_kernel(
    const float* __restrict__ x,
    const float* __restrict__ w_ih1, const float* __restrict__ w_hh1,
    const float* __restrict__ b_ih1, const float* __restrict__ b_hh1,
    const float* __restrict__ w_ih2, const float* __restrict__ w_hh2,
    const float* __restrict__ b_ih2, const float* __restrict__ b_hh2,
    const float* __restrict__ fc_w, const float* __restrict__ fc_b,
    float* __restrict__ out, int B)
{
    const int tid = blockIdx.x * blockDim.x + threadIdx.x;
    const int b   = tid >> 3;
    if (b >= B) return;
    const int j   = tid & 7;
    const unsigned FULL = 0xffffffffu;

    const int gi = j, gf = j + 8, gg = j + 16, go = j + 24;

    // Scale factors: sigmoid rows (i,f,o) get 0.5 (tanh half-angle);
    // h-consuming weights get an extra 0.5 (h stored as 2h).
    const float SH = 0.25f;   // sigmoid row on h input
    const float TH = 0.5f;    // tanh row on h input
    const float SX = 0.5f;    // sigmoid row on x input
    const float TX = 1.0f;    // tanh row on x input

    // ---- fold scales into packed weights (one-time) ----
    u64 whIF1[8], whGO1[8], wxIF2[8], wxGO2[8], whIF2[8], whGO2[8];
    #pragma unroll
    for (int k = 0; k < 8; k++) {
        whIF1[k] = pk(SH * w_hh1[gi*8+k], SH * w_hh1[gf*8+k]);
        whGO1[k] = pk(TH * w_hh1[gg*8+k], SH * w_hh1[go*8+k]);
        wxIF2[k] = pk(SH * w_ih2[gi*8+k], SH * w_ih2[gf*8+k]);
        wxGO2[k] = pk(TH * w_ih2[gg*8+k], SH * w_ih2[go*8+k]);
        whIF2[k] = pk(SH * w_hh2[gi*8+k], SH * w_hh2[gf*8+k]);
        whGO2[k] = pk(TH * w_hh2[gg*8+k], SH * w_hh2[go*8+k]);
    }
    const u64 wx1IF = pk(SX * w_ih1[gi], SX * w_ih1[gf]);
    const u64 wx1GO = pk(TX * w_ih1[gg], SX * w_ih1[go]);
    const u64 bIF1  = pk(SX*(b_ih1[gi]+b_hh1[gi]), SX*(b_ih1[gf]+b_hh1[gf]));
    const u64 bGO1  = pk(TX*(b_ih1[gg]+b_hh1[gg]), SX*(b_ih1[go]+b_hh1[go]));
    const u64 bIF2  = pk(SX*(b_ih2[gi]+b_hh2[gi]), SX*(b_ih2[gf]+b_hh2[gf]));
    const u64 bGO2  = pk(TX*(b_ih2[gg]+b_hh2[gg]), SX*(b_ih2[go]+b_hh2[go]));

    // ---- SMEM h-exchange: [parity][group][H1: 0..7 | H2: 8..15], pad to 17 ----
    __shared__ __align__(16) u64 hb[2][16][17];
    const int grp = threadIdx.x >> 3;         // group within CTA (0..15)

    // ---- state ----
    float c1 = 0.0f, c2 = 0.0f;

    const float* xb = x + (size_t)b * T_LEN;

    // ---- prologue (t=0): L1 step 0 (h1=c1=0); h2(-1)=0. Writes parity 0 ----
    {
        const float x0 = __ldg(&xb[0]);
        float ai, af, ag, ao;
        unpk(fma2_(wx1IF, pk(x0, x0), bIF1), ai, af);
        unpk(fma2_(wx1GO, pk(x0, x0), bGO1), ag, ao);
        const float h1x = lstm_act(ai, af, ag, ao, c1);
        float* s1 = (float*)&hb[0][grp][j];
        float* s2 = (float*)&hb[0][grp][8 + j];
        s1[0] = h1x; s1[1] = h1x;
        s2[0] = 0.f; s2[1] = 0.f;
        __syncwarp();
    }

    float xt_next = __ldg(&xb[1]);

    // ---- main loop: iteration t computes L1(t) and L2(t-1) ----
    #pragma unroll 2
    for (int t = 1; t < T_LEN; t++) {
        const float xt = xt_next;
        xt_next = __ldg(&xb[(t + 1) & (T_LEN - 1)]);   // wraps harmlessly
        const int q = (t - 1) & 1, p = t & 1;

        // load h vectors written by previous step (duplicated-packed u64s)
        const u64* hv = &hb[q][grp][0];
        u64 H1[8], H2[8];
        #pragma unroll
        for (int k = 0; k < 8; k++) { H1[k] = hv[k]; H2[k] = hv[8 + k]; }

        const u64 XT = pk(xt, xt);

        // L1(t) pre-acts: b1 + wx1*x + wh1 . H1 (two parallel 4/5-chains)
        u64 aIF0 = fma2_(wx1IF, XT, bIF1);
        u64 aGO0 = fma2_(wx1GO, XT, bGO1);
        #pragma unroll
        for (int k = 0; k < 4; k++) {
            aIF0 = fma2_(whIF1[k], H1[k], aIF0);
            aGO0 = fma2_(whGO1[k], H1[k], aGO0);
        }
        u64 aIF1 = mul2_(whIF1[4], H1[4]);
        u64 aGO1 = mul2_(whGO1[4], H1[4]);
        #pragma unroll
        for (int k = 5; k < 8; k++) {
            aIF1 = fma2_(whIF1[k], H1[k], aIF1);
            aGO1 = fma2_(whGO1[k], H1[k], aGO1);
        }

        // L2(t-1) pre-acts: b2 + wh2 . H2 + wx2 . H1 (two parallel 8-chains)
        u64 eIF0 = bIF2, eGO0 = bGO2;
        #pragma unroll
        for (int k = 0; k < 8; k++) {
            eIF0 = fma2_(whIF2[k], H2[k], eIF0);
            eGO0 = fma2_(whGO2[k], H2[k], eGO0);
        }
        u64 eIF1 = mul2_(wxIF2[0], H1[0]);
        u64 eGO1 = mul2_(wxGO2[0], H1[0]);
        #pragma unroll
        for (int k = 1; k < 8; k++) {
            eIF1 = fma2_(wxIF2[k], H1[k], eIF1);
            eGO1 = fma2_(wxGO2[k], H1[k], eGO1);
        }

        // ---- activations ----
        float a_i, a_f, a_g, a_o;
        unpk(add2_(aIF0, aIF1), a_i, a_f);
        unpk(add2_(aGO0, aGO1), a_g, a_o);
        const float h1x = lstm_act(a_i, a_f, a_g, a_o, c1);

        float e_i, e_f, e_g, e_o;
        unpk(add2_(eIF0, eIF1), e_i, e_f);
        unpk(add2_(eGO0, eGO1), e_g, e_o);
        const float h2x = lstm_act(e_i, e_f, e_g, e_o, c2);

        // ---- store duplicated h values for next step (parity p) ----
        float* s1 = (float*)&hb[p][grp][j];
        float* s2 = (float*)&hb[p][grp][8 + j];
        s1[0] = h1x; s1[1] = h1x;
        s2[0] = h2x; s2[1] = h2x;
        __syncwarp();
    }

    // ---- epilogue: L2(T-1). Last store was parity 1 ----
    float h2last;
    {
        const u64* hv = &hb[1][grp][0];
        u64 H1[8], H2[8];
        #pragma unroll
        for (int k = 0; k < 8; k++) { H1[k] = hv[k]; H2[k] = hv[8 + k]; }

        u64 eIF0 = bIF2, eGO0 = bGO2;
        #pragma unroll
        for (int k = 0; k < 8; k++) {
            eIF0 = fma2_(whIF2[k], H2[k], eIF0);
            eGO0 = fma2_(whGO2[k], H2[k], eGO0);
        }
        u64 eIF1 = mul2_(wxIF2[0], H1[0]);
        u64 eGO1 = mul2_(wxGO2[0], H1[0]);
        #pragma unroll
        for (int k = 1; k < 8; k++) {
            eIF1 = fma2_(wxIF2[k], H1[k], eIF1);
            eGO1 = fma2_(wxGO2[k], H1[k], eGO1);
        }
        float e_i, e_f, e_g, e_o;
        unpk(add2_(eIF0, eIF1), e_i, e_f);
        unpk(add2_(eGO0, eGO1), e_g, e_o);
        h2last = lstm_act(e_i, e_f, e_g, e_o, c2);    // h2x of final step
    }

    // ---- fc on final h2 (h stored as 2h -> fc_w pre-halved) ----
    float h2f[8];
    #pragma unroll
    for (int k = 0; k < 8; k++) h2f[k] = __shfl_sync(FULL, h2last, k, 8);
    if (j < 4) {
        float acc = fc_b[j];
        #pragma unroll
        for (int k = 0; k < 8; k++) acc = fmaf(0.5f * fc_w[j*8+k], h2f[k], acc);
        out[b*4 + j] = acc;
    }
}

extern "C" void kernel_launch(void* const* d_in, const int* in_sizes, int n_in,
                              void* d_out, int out_size)
{
    const float* x     = (const float*)d_in[0];
    const float* w_ih1 = (const float*)d_in[1];
    const float* w_hh1 = (const float*)d_in[2];
    const float* b_ih1 = (const float*)d_in[3];
    const float* b_hh1 = (const float*)d_in[4];
    const float* w_ih2 = (const float*)d_in[5];
    const float* w_hh2 = (const float*)d_in[6];
    const float* b_ih2 = (const float*)d_in[7];
    const float* b_hh2 = (const float*)d_in[8];
    const float* fc_w  = (const float*)d_in[9];
    const float* fc_b  = (const float*)d_in[10];
    float* out = (float*)d_out;

    const int B = in_sizes[0] / T_LEN;      // 4096
    const int threads = B * 8;              // 8 lanes per batch element
    const int block = 128;                  // best-known config
    const int grid = (threads + block - 1) / block;

    lstm2_fused_kernel<<<grid, block>>>(x, w_ih1, w_hh1, b_ih1, b_hh1,
                                        w_ih2, w_hh2, b_ih2, b_hh2,
                                        fc_w, fc_b, out, B);
}